// round 13
// baseline (speedup 1.0000x reference)
#include <cuda_runtime.h>
#include <cuda_bf16.h>
#include <cstdint>

namespace {
constexpr int S  = 8192;
constexpr int D  = 64;
constexpr int TQ = 64;             // queries per CTA
constexpr int KR = 192;            // key rows per CTA
constexpr int NT = 128;            // 4 warps x 16 query rows
constexpr int NCH = 6;             // 6 chunks x 32 keys

constexpr int SM_QH = 0;           // bf16 tiles, 128 B/row, swizzled
constexpr int SM_QL = 8192;
constexpr int SM_KH = 16384;
constexpr int SM_KL = 40960;
constexpr int SM_VH = 65536;
constexpr int SM_VL = 90112;
constexpr int SMEM_BYTES = 114688; // 112 KB -> 2 CTAs/SM
}

__device__ __forceinline__ uint32_t smem_u32(const void* p) {
    uint32_t a;
    asm("{ .reg .u64 t; cvta.to.shared.u64 t, %1; cvt.u32.u64 %0, t; }" : "=r"(a) : "l"(p));
    return a;
}
__device__ __forceinline__ uint32_t tile_addr(uint32_t base, int row, int c16) {
    return base + row * 128 + ((uint32_t)(c16 ^ (row & 7)) << 4);
}
__device__ __forceinline__ void split2(float x0, float x1, uint32_t& hi, uint32_t& lo) {
    __nv_bfloat16 h0 = __float2bfloat16(x0);
    __nv_bfloat16 h1 = __float2bfloat16(x1);
    __nv_bfloat16 l0 = __float2bfloat16(x0 - __bfloat162float(h0));
    __nv_bfloat16 l1 = __float2bfloat16(x1 - __bfloat162float(h1));
    hi = (uint32_t)__bfloat16_as_ushort(h0) | ((uint32_t)__bfloat16_as_ushort(h1) << 16);
    lo = (uint32_t)__bfloat16_as_ushort(l0) | ((uint32_t)__bfloat16_as_ushort(l1) << 16);
}
__device__ __forceinline__ void ldsm4(uint32_t& r0, uint32_t& r1, uint32_t& r2, uint32_t& r3,
                                      uint32_t addr) {
    asm volatile("ldmatrix.sync.aligned.m8n8.x4.shared.b16 {%0,%1,%2,%3}, [%4];"
                 : "=r"(r0), "=r"(r1), "=r"(r2), "=r"(r3) : "r"(addr));
}
__device__ __forceinline__ void ldsm4t(uint32_t& r0, uint32_t& r1, uint32_t& r2, uint32_t& r3,
                                       uint32_t addr) {
    asm volatile("ldmatrix.sync.aligned.m8n8.x4.trans.shared.b16 {%0,%1,%2,%3}, [%4];"
                 : "=r"(r0), "=r"(r1), "=r"(r2), "=r"(r3) : "r"(addr));
}
__device__ __forceinline__ void mma16816(float* d, const uint32_t* a, uint32_t b0, uint32_t b1) {
    asm volatile("mma.sync.aligned.m16n8k16.row.col.f32.bf16.bf16.f32 "
                 "{%0,%1,%2,%3}, {%4,%5,%6,%7}, {%8,%9}, {%0,%1,%2,%3};"
                 : "+f"(d[0]), "+f"(d[1]), "+f"(d[2]), "+f"(d[3])
                 : "r"(a[0]), "r"(a[1]), "r"(a[2]), "r"(a[3]), "r"(b0), "r"(b1));
}

// score GEMM for one 32-key chunk (standalone, used for chunk 0)
__device__ __forceinline__ void score32(
    uint32_t sb, int kbase, int mat, int lrow,
    const uint32_t (&qh)[4][4], const uint32_t (&ql)[4][4],
    float (&sc)[4][4]) {
    #pragma unroll
    for (int j = 0; j < 4; ++j)
        #pragma unroll
        for (int e = 0; e < 4; ++e) sc[j][e] = 0.f;
    #pragma unroll
    for (int u = 0; u < 8; ++u) {
        int g2 = u >> 2, ks = u & 3;
        int krow = kbase + g2 * 16 + ((mat >> 1) & 1) * 8 + lrow;
        int c16  = ks * 2 + (mat & 1);
        uint32_t b0, b1, b2, b3;
        ldsm4(b0, b1, b2, b3, tile_addr(sb + SM_KH, krow, c16));
        mma16816(sc[2 * g2],     qh[ks], b0, b1);
        mma16816(sc[2 * g2 + 1], qh[ks], b2, b3);
        mma16816(sc[2 * g2],     ql[ks], b0, b1);
        mma16816(sc[2 * g2 + 1], ql[ks], b2, b3);
        uint32_t x0, x1, x2, x3;
        ldsm4(x0, x1, x2, x3, tile_addr(sb + SM_KL, krow, c16));
        mma16816(sc[2 * g2],     qh[ks], x0, x1);
        mma16816(sc[2 * g2 + 1], qh[ks], x2, x3);
    }
}

// one pipeline stage: exp(cur) -> sigma; then PV(cur) interleaved with score(next chunk)
__device__ __forceinline__ void chunk_body(
    uint32_t sb, int kbase, int mat, int lrow, int c,
    int lo0, int hi0, int lo1, int hi1,
    const uint32_t (&qh)[4][4], const uint32_t (&ql)[4][4],
    float (&cur)[4][4], float (&nxt)[4][4],
    float (&oacc)[8][4], float& sig0, float& sig1, bool do_score) {

    // masked exp (no max-sub)
    #pragma unroll
    for (int j = 0; j < 4; ++j) {
        int col0 = kbase + 8 * j + 2 * c;
        int col1 = col0 + 1;
        float e0 = (col0 >= lo0 && col0 <= hi0) ? __expf(cur[j][0] * 0.125f) : 0.f;
        float e1 = (col1 >= lo0 && col1 <= hi0) ? __expf(cur[j][1] * 0.125f) : 0.f;
        float e2 = (col0 >= lo1 && col0 <= hi1) ? __expf(cur[j][2] * 0.125f) : 0.f;
        float e3 = (col1 >= lo1 && col1 <= hi1) ? __expf(cur[j][3] * 0.125f) : 0.f;
        sig0 += e0 + e1;
        sig1 += e2 + e3;
        cur[j][0] = e0; cur[j][1] = e1; cur[j][2] = e2; cur[j][3] = e3;
    }

    if (do_score) {
        #pragma unroll
        for (int j = 0; j < 4; ++j)
            #pragma unroll
            for (int e = 0; e < 4; ++e) nxt[j][e] = 0.f;
    }

    const int kbn = kbase + 32;
    uint32_t ah[4], al[4];
    #pragma unroll
    for (int u = 0; u < 8; ++u) {
        const int kk = u >> 2, g = u & 3;
        if (g == 0) {
            split2(cur[2 * kk][0],     cur[2 * kk][1],     ah[0], al[0]);
            split2(cur[2 * kk][2],     cur[2 * kk][3],     ah[1], al[1]);
            split2(cur[2 * kk + 1][0], cur[2 * kk + 1][1], ah[2], al[2]);
            split2(cur[2 * kk + 1][2], cur[2 * kk + 1][3], ah[3], al[3]);
        }
        // ---- PV unit: keys [kbase+16kk, +16), output cols [16g, 16g+16)
        {
            int vrow = kbase + kk * 16 + (mat & 1) * 8 + lrow;
            int c16  = g * 2 + (mat >> 1);
            uint32_t v0, v1, v2, v3;
            ldsm4t(v0, v1, v2, v3, tile_addr(sb + SM_VH, vrow, c16));
            mma16816(oacc[2 * g],     ah, v0, v1);
            mma16816(oacc[2 * g + 1], ah, v2, v3);
            mma16816(oacc[2 * g],     al, v0, v1);
            mma16816(oacc[2 * g + 1], al, v2, v3);
            uint32_t w0, w1, w2, w3;
            ldsm4t(w0, w1, w2, w3, tile_addr(sb + SM_VL, vrow, c16));
            mma16816(oacc[2 * g],     ah, w0, w1);
            mma16816(oacc[2 * g + 1], ah, w2, w3);
        }
        // ---- score unit for next chunk (register-independent of PV unit)
        if (do_score) {
            int g2 = u >> 2, ks = u & 3;
            int krow = kbn + g2 * 16 + ((mat >> 1) & 1) * 8 + lrow;
            int c16  = ks * 2 + (mat & 1);
            uint32_t b0, b1, b2, b3;
            ldsm4(b0, b1, b2, b3, tile_addr(sb + SM_KH, krow, c16));
            mma16816(nxt[2 * g2],     qh[ks], b0, b1);
            mma16816(nxt[2 * g2 + 1], qh[ks], b2, b3);
            mma16816(nxt[2 * g2],     ql[ks], b0, b1);
            mma16816(nxt[2 * g2 + 1], ql[ks], b2, b3);
            uint32_t x0, x1, x2, x3;
            ldsm4(x0, x1, x2, x3, tile_addr(sb + SM_KL, krow, c16));
            mma16816(nxt[2 * g2],     qh[ks], x0, x1);
            mma16816(nxt[2 * g2 + 1], qh[ks], x2, x3);
        }
    }
}

__global__ __launch_bounds__(NT, 2)
void swa_mma_kernel(const float* __restrict__ Q,
                    const float* __restrict__ K,
                    const float* __restrict__ V,
                    float* __restrict__ O) {
    extern __shared__ char smem[];
    const uint32_t sb = smem_u32(smem);
    const int t = threadIdx.x;

    const int tile = blockIdx.x;
    const int b  = tile >> 7;              // 128 tiles per batch
    const int qt = (tile & 127) * TQ;
    const int KB = qt - 64;

    const float* qb = Q + (size_t)b * S * D;
    const float* kb = K + (size_t)b * S * D;
    const float* vb = V + (size_t)b * S * D;

    // ---------------- stage fp32 -> bf16 hi/lo tiles (swizzled) -----------
    for (int idx = t; idx < TQ * 32; idx += NT) {
        int row = idx >> 5, d2 = idx & 31;
        float2 f = *(const float2*)(qb + (size_t)(qt + row) * D + 2 * d2);
        uint32_t hi, lo;  split2(f.x, f.y, hi, lo);
        uint32_t off = row * 128 + (((uint32_t)((d2 >> 2) ^ (row & 7))) << 4) + (d2 & 3) * 4;
        *(uint32_t*)(smem + SM_QH + off) = hi;
        *(uint32_t*)(smem + SM_QL + off) = lo;
    }
    for (int idx = t; idx < KR * 32; idx += NT) {
        int row = idx >> 5, d2 = idx & 31;
        int kg = KB + row;
        float2 fk = make_float2(0.f, 0.f), fv = make_float2(0.f, 0.f);
        if (kg >= 0 && kg < S) {
            fk = *(const float2*)(kb + (size_t)kg * D + 2 * d2);
            fv = *(const float2*)(vb + (size_t)kg * D + 2 * d2);
        }
        uint32_t off = row * 128 + (((uint32_t)((d2 >> 2) ^ (row & 7))) << 4) + (d2 & 3) * 4;
        uint32_t hi, lo;
        split2(fk.x, fk.y, hi, lo);
        *(uint32_t*)(smem + SM_KH + off) = hi;
        *(uint32_t*)(smem + SM_KL + off) = lo;
        split2(fv.x, fv.y, hi, lo);
        *(uint32_t*)(smem + SM_VH + off) = hi;
        *(uint32_t*)(smem + SM_VL + off) = lo;
    }
    __syncthreads();

    const int lane = t & 31;
    const int w    = t >> 5;
    const int r    = lane >> 2;
    const int c    = lane & 3;
    const int rl0  = w * 16 + r;
    const int rl1  = rl0 + 8;
    const int mat  = lane >> 3;
    const int lrow = lane & 7;

    const int lo0 = max(rl0, -KB), hi0 = min(rl0 + 128, S - 1 - KB);
    const int lo1 = max(rl1, -KB), hi1 = min(rl1 + 128, S - 1 - KB);

    // Q A-fragments (persist)
    uint32_t qh[4][4], ql[4][4];
    {
        int qrow = w * 16 + (mat & 1) * 8 + lrow;
        #pragma unroll
        for (int ks = 0; ks < 4; ++ks) {
            int c16 = ks * 2 + (mat >> 1);
            ldsm4(qh[ks][0], qh[ks][1], qh[ks][2], qh[ks][3],
                  tile_addr(sb + SM_QH, qrow, c16));
            ldsm4(ql[ks][0], ql[ks][1], ql[ks][2], ql[ks][3],
                  tile_addr(sb + SM_QL, qrow, c16));
        }
    }

    float oacc[8][4];
    #pragma unroll
    for (int j = 0; j < 8; ++j)
        #pragma unroll
        for (int e = 0; e < 4; ++e) oacc[j][e] = 0.f;
    float sig0 = 0.f, sig1 = 0.f;

    float sA[4][4], sB[4][4];
    score32(sb, 0, mat, lrow, qh, ql, sA);      // prologue: scores of chunk 0

    #pragma unroll
    for (int ch = 0; ch < NCH; ++ch) {
        bool ds = (ch < NCH - 1);
        if (ch & 1)
            chunk_body(sb, 32 * ch, mat, lrow, c, lo0, hi0, lo1, hi1,
                       qh, ql, sB, sA, oacc, sig0, sig1, ds);
        else
            chunk_body(sb, 32 * ch, mat, lrow, c, lo0, hi0, lo1, hi1,
                       qh, ql, sA, sB, oacc, sig0, sig1, ds);
    }

    // ---------------- normalize + write -----------------------------------
    sig0 += __shfl_xor_sync(0xffffffffu, sig0, 1);
    sig0 += __shfl_xor_sync(0xffffffffu, sig0, 2);
    sig1 += __shfl_xor_sync(0xffffffffu, sig1, 1);
    sig1 += __shfl_xor_sync(0xffffffffu, sig1, 2);
    float rinv0 = 1.f / sig0;
    float rinv1 = 1.f / sig1;

    float* o0 = O + ((size_t)b * S + qt + rl0) * D;
    float* o1 = O + ((size_t)b * S + qt + rl1) * D;
    #pragma unroll
    for (int j = 0; j < 8; ++j) {
        *(float2*)(o0 + 8 * j + 2 * c) = make_float2(oacc[j][0] * rinv0, oacc[j][1] * rinv0);
        *(float2*)(o1 + 8 * j + 2 * c) = make_float2(oacc[j][2] * rinv1, oacc[j][3] * rinv1);
    }
}

extern "C" void kernel_launch(void* const* d_in, const int* in_sizes, int n_in,
                              void* d_out, int out_size) {
    const float* q = (const float*)d_in[0];
    const float* k = (const float*)d_in[1];
    const float* v = (const float*)d_in[2];
    float* o = (float*)d_out;
    (void)n_in; (void)out_size;

    cudaFuncSetAttribute(swa_mma_kernel,
                         cudaFuncAttributeMaxDynamicSharedMemorySize, SMEM_BYTES);
    const int B = in_sizes[0] / (S * D);           // 2
    swa_mma_kernel<<<B * (S / TQ), NT, SMEM_BYTES>>>(q, k, v, o);
}

// round 14
// speedup vs baseline: 1.2020x; 1.2020x over previous
#include <cuda_runtime.h>
#include <cuda_bf16.h>
#include <cstdint>

namespace {
constexpr int S  = 8192;
constexpr int D  = 64;
constexpr int TQ = 64;             // queries per CTA
constexpr int KR = 192;            // key rows per CTA
constexpr int NT = 256;            // 8 warps: pair i owns rows [16i,16i+16); even=keys 0-95, odd=96-191

constexpr int SM_QH = 0;           // bf16 tiles, 128 B/row, swizzled
constexpr int SM_QL = 8192;
constexpr int SM_KH = 16384;       // 192*128 = 24576
constexpr int SM_KL = 40960;
constexpr int SM_VH = 65536;
constexpr int SM_VL = 90112;
constexpr int SMEM_BYTES = 114688; // 112 KB -> 2 CTAs/SM
// pair-reduction scratch reuses the K-hi tile after compute
constexpr int SM_RED = SM_KH;      // [64][72] floats (stride 72 kills row conflicts)
constexpr int SM_SIG = SM_KH + 72 * 64 * 4;
}

__device__ __forceinline__ uint32_t smem_u32(const void* p) {
    uint32_t a;
    asm("{ .reg .u64 t; cvta.to.shared.u64 t, %1; cvt.u32.u64 %0, t; }" : "=r"(a) : "l"(p));
    return a;
}
__device__ __forceinline__ uint32_t tile_addr(uint32_t base, int row, int c16) {
    return base + row * 128 + ((uint32_t)(c16 ^ (row & 7)) << 4);
}
__device__ __forceinline__ void split2(float x0, float x1, uint32_t& hi, uint32_t& lo) {
    __nv_bfloat16 h0 = __float2bfloat16(x0);
    __nv_bfloat16 h1 = __float2bfloat16(x1);
    __nv_bfloat16 l0 = __float2bfloat16(x0 - __bfloat162float(h0));
    __nv_bfloat16 l1 = __float2bfloat16(x1 - __bfloat162float(h1));
    hi = (uint32_t)__bfloat16_as_ushort(h0) | ((uint32_t)__bfloat16_as_ushort(h1) << 16);
    lo = (uint32_t)__bfloat16_as_ushort(l0) | ((uint32_t)__bfloat16_as_ushort(l1) << 16);
}
__device__ __forceinline__ void ldsm4(uint32_t& r0, uint32_t& r1, uint32_t& r2, uint32_t& r3,
                                      uint32_t addr) {
    asm volatile("ldmatrix.sync.aligned.m8n8.x4.shared.b16 {%0,%1,%2,%3}, [%4];"
                 : "=r"(r0), "=r"(r1), "=r"(r2), "=r"(r3) : "r"(addr));
}
__device__ __forceinline__ void ldsm4t(uint32_t& r0, uint32_t& r1, uint32_t& r2, uint32_t& r3,
                                       uint32_t addr) {
    asm volatile("ldmatrix.sync.aligned.m8n8.x4.trans.shared.b16 {%0,%1,%2,%3}, [%4];"
                 : "=r"(r0), "=r"(r1), "=r"(r2), "=r"(r3) : "r"(addr));
}
__device__ __forceinline__ void mma16816(float* d, const uint32_t* a, uint32_t b0, uint32_t b1) {
    asm volatile("mma.sync.aligned.m16n8k16.row.col.f32.bf16.bf16.f32 "
                 "{%0,%1,%2,%3}, {%4,%5,%6,%7}, {%8,%9}, {%0,%1,%2,%3};"
                 : "+f"(d[0]), "+f"(d[1]), "+f"(d[2]), "+f"(d[3])
                 : "r"(a[0]), "r"(a[1]), "r"(a[2]), "r"(a[3]), "r"(b0), "r"(b1));
}

__global__ __launch_bounds__(NT, 2)
void swa_mma_kernel(const float* __restrict__ Q,
                    const float* __restrict__ K,
                    const float* __restrict__ V,
                    float* __restrict__ O) {
    extern __shared__ char smem[];
    const uint32_t sb = smem_u32(smem);
    const int t = threadIdx.x;

    const int tile = blockIdx.x;
    const int b  = tile >> 7;              // 128 tiles per batch
    const int qt = (tile & 127) * TQ;
    const int KB = qt - 64;

    const float* qb = Q + (size_t)b * S * D;
    const float* kb = K + (size_t)b * S * D;
    const float* vb = V + (size_t)b * S * D;

    // ---------------- stage fp32 -> bf16 hi/lo tiles (swizzled) -----------
    for (int idx = t; idx < TQ * 32; idx += NT) {
        int row = idx >> 5, d2 = idx & 31;
        float2 f = *(const float2*)(qb + (size_t)(qt + row) * D + 2 * d2);
        uint32_t hi, lo;  split2(f.x, f.y, hi, lo);
        uint32_t off = row * 128 + (((uint32_t)((d2 >> 2) ^ (row & 7))) << 4) + (d2 & 3) * 4;
        *(uint32_t*)(smem + SM_QH + off) = hi;
        *(uint32_t*)(smem + SM_QL + off) = lo;
    }
    for (int idx = t; idx < KR * 32; idx += NT) {
        int row = idx >> 5, d2 = idx & 31;
        int kg = KB + row;
        float2 fk = make_float2(0.f, 0.f), fv = make_float2(0.f, 0.f);
        if (kg >= 0 && kg < S) {
            fk = *(const float2*)(kb + (size_t)kg * D + 2 * d2);
            fv = *(const float2*)(vb + (size_t)kg * D + 2 * d2);
        }
        uint32_t off = row * 128 + (((uint32_t)((d2 >> 2) ^ (row & 7))) << 4) + (d2 & 3) * 4;
        uint32_t hi, lo;
        split2(fk.x, fk.y, hi, lo);
        *(uint32_t*)(smem + SM_KH + off) = hi;
        *(uint32_t*)(smem + SM_KL + off) = lo;
        split2(fv.x, fv.y, hi, lo);
        *(uint32_t*)(smem + SM_VH + off) = hi;
        *(uint32_t*)(smem + SM_VL + off) = lo;
    }
    __syncthreads();

    const int lane = t & 31;
    const int w    = t >> 5;               // 0..7
    const int pair = w >> 1;               // 0..3: query rows [16*pair, +16)
    const int kw   = (w & 1) * 96;         // this warp's key sub-range base
    const int r    = lane >> 2;
    const int c    = lane & 3;
    const int rl0  = pair * 16 + r;
    const int rl1  = rl0 + 8;
    const int mat  = lane >> 3;
    const int lrow = lane & 7;

    const int lo0 = max(rl0, -KB), hi0 = min(rl0 + 128, S - 1 - KB);
    const int lo1 = max(rl1, -KB), hi1 = min(rl1 + 128, S - 1 - KB);

    // ---------------- Q A-fragments (persist) -----------------------------
    uint32_t qh[4][4], ql[4][4];
    {
        int qrow = pair * 16 + (mat & 1) * 8 + lrow;
        #pragma unroll
        for (int ks = 0; ks < 4; ++ks) {
            int c16 = ks * 2 + (mat >> 1);
            ldsm4(qh[ks][0], qh[ks][1], qh[ks][2], qh[ks][3],
                  tile_addr(sb + SM_QH, qrow, c16));
            ldsm4(ql[ks][0], ql[ks][1], ql[ks][2], ql[ks][3],
                  tile_addr(sb + SM_QL, qrow, c16));
        }
    }

    float oacc[8][4];
    #pragma unroll
    for (int j = 0; j < 8; ++j)
        #pragma unroll
        for (int e = 0; e < 4; ++e) oacc[j][e] = 0.f;
    float sig0 = 0.f, sig1 = 0.f;

    #pragma unroll
    for (int ch = 0; ch < 3; ++ch) {
        const int kbase = kw + 32 * ch;

        // ---- scores: S = Qh*Kh + Ql*Kh + Qh*Kl  (16 x 32 per warp) -------
        float sacc[4][4];
        #pragma unroll
        for (int j = 0; j < 4; ++j)
            #pragma unroll
            for (int e = 0; e < 4; ++e) sacc[j][e] = 0.f;

        #pragma unroll
        for (int u = 0; u < 8; ++u) {
            int g2 = u >> 2, ks = u & 3;
            int krow = kbase + g2 * 16 + ((mat >> 1) & 1) * 8 + lrow;
            int c16  = ks * 2 + (mat & 1);
            uint32_t b0, b1, b2, b3;
            ldsm4(b0, b1, b2, b3, tile_addr(sb + SM_KH, krow, c16));
            mma16816(sacc[2 * g2],     qh[ks], b0, b1);
            mma16816(sacc[2 * g2 + 1], qh[ks], b2, b3);
            mma16816(sacc[2 * g2],     ql[ks], b0, b1);
            mma16816(sacc[2 * g2 + 1], ql[ks], b2, b3);
            uint32_t x0, x1, x2, x3;
            ldsm4(x0, x1, x2, x3, tile_addr(sb + SM_KL, krow, c16));
            mma16816(sacc[2 * g2],     qh[ks], x0, x1);
            mma16816(sacc[2 * g2 + 1], qh[ks], x2, x3);
        }

        // ---- masked exp (no max-sub) -------------------------------------
        #pragma unroll
        for (int j = 0; j < 4; ++j) {
            int col0 = kbase + 8 * j + 2 * c;
            int col1 = col0 + 1;
            float e0 = (col0 >= lo0 && col0 <= hi0) ? __expf(sacc[j][0] * 0.125f) : 0.f;
            float e1 = (col1 >= lo0 && col1 <= hi0) ? __expf(sacc[j][1] * 0.125f) : 0.f;
            float e2 = (col0 >= lo1 && col0 <= hi1) ? __expf(sacc[j][2] * 0.125f) : 0.f;
            float e3 = (col1 >= lo1 && col1 <= hi1) ? __expf(sacc[j][3] * 0.125f) : 0.f;
            sig0 += e0 + e1;
            sig1 += e2 + e3;
            sacc[j][0] = e0; sacc[j][1] = e1; sacc[j][2] = e2; sacc[j][3] = e3;
        }

        // ---- PV: O += Ph*Vh + Pl*Vh + Ph*Vl ------------------------------
        #pragma unroll
        for (int kk = 0; kk < 2; ++kk) {
            uint32_t ah[4], al[4];
            split2(sacc[2 * kk][0],     sacc[2 * kk][1],     ah[0], al[0]);
            split2(sacc[2 * kk][2],     sacc[2 * kk][3],     ah[1], al[1]);
            split2(sacc[2 * kk + 1][0], sacc[2 * kk + 1][1], ah[2], al[2]);
            split2(sacc[2 * kk + 1][2], sacc[2 * kk + 1][3], ah[3], al[3]);
            int vrow = kbase + kk * 16 + (mat & 1) * 8 + lrow;
            #pragma unroll
            for (int g = 0; g < 4; ++g) {
                int c16 = g * 2 + (mat >> 1);
                uint32_t v0, v1, v2, v3;
                ldsm4t(v0, v1, v2, v3, tile_addr(sb + SM_VH, vrow, c16));
                mma16816(oacc[2 * g],     ah, v0, v1);
                mma16816(oacc[2 * g + 1], ah, v2, v3);
                mma16816(oacc[2 * g],     al, v0, v1);
                mma16816(oacc[2 * g + 1], al, v2, v3);
                uint32_t w0, w1, w2, w3;
                ldsm4t(w0, w1, w2, w3, tile_addr(sb + SM_VL, vrow, c16));
                mma16816(oacc[2 * g],     ah, w0, w1);
                mma16816(oacc[2 * g + 1], ah, w2, w3);
            }
        }
    }

    // ---------------- quad-reduce sigma ------------------------------------
    sig0 += __shfl_xor_sync(0xffffffffu, sig0, 1);
    sig0 += __shfl_xor_sync(0xffffffffu, sig0, 2);
    sig1 += __shfl_xor_sync(0xffffffffu, sig1, 1);
    sig1 += __shfl_xor_sync(0xffffffffu, sig1, 2);

    // ---------------- pair reduction through smem (K tile is dead) ---------
    __syncthreads();
    float* red  = (float*)(smem + SM_RED);   // [64][72]
    float* rsig = (float*)(smem + SM_SIG);   // [64]
    if (w & 1) {
        #pragma unroll
        for (int j = 0; j < 8; ++j) {
            *(float2*)(red + rl0 * 72 + 8 * j + 2 * c) = make_float2(oacc[j][0], oacc[j][1]);
            *(float2*)(red + rl1 * 72 + 8 * j + 2 * c) = make_float2(oacc[j][2], oacc[j][3]);
        }
        if (c == 0) { rsig[rl0] = sig0; rsig[rl1] = sig1; }
    }
    __syncthreads();
    if (!(w & 1)) {
        float rinv0 = 1.f / (sig0 + rsig[rl0]);
        float rinv1 = 1.f / (sig1 + rsig[rl1]);
        float* o0 = O + ((size_t)b * S + qt + rl0) * D;
        float* o1 = O + ((size_t)b * S + qt + rl1) * D;
        #pragma unroll
        for (int j = 0; j < 8; ++j) {
            float2 a0 = *(float2*)(red + rl0 * 72 + 8 * j + 2 * c);
            float2 a1 = *(float2*)(red + rl1 * 72 + 8 * j + 2 * c);
            *(float2*)(o0 + 8 * j + 2 * c) =
                make_float2((oacc[j][0] + a0.x) * rinv0, (oacc[j][1] + a0.y) * rinv0);
            *(float2*)(o1 + 8 * j + 2 * c) =
                make_float2((oacc[j][2] + a1.x) * rinv1, (oacc[j][3] + a1.y) * rinv1);
        }
    }
}

extern "C" void kernel_launch(void* const* d_in, const int* in_sizes, int n_in,
                              void* d_out, int out_size) {
    const float* q = (const float*)d_in[0];
    const float* k = (const float*)d_in[1];
    const float* v = (const float*)d_in[2];
    float* o = (float*)d_out;
    (void)n_in; (void)out_size;

    cudaFuncSetAttribute(swa_mma_kernel,
                         cudaFuncAttributeMaxDynamicSharedMemorySize, SMEM_BYTES);
    const int B = in_sizes[0] / (S * D);           // 2
    swa_mma_kernel<<<B * (S / TQ), NT, SMEM_BYTES>>>(q, k, v, o);
}

// round 15
// speedup vs baseline: 1.2183x; 1.0135x over previous
#include <cuda_runtime.h>
#include <cuda_bf16.h>
#include <cstdint>

namespace {
constexpr int S  = 8192;
constexpr int D  = 64;
constexpr int TQ = 64;             // queries per CTA
constexpr int KR = 192;            // key rows per CTA
constexpr int NT = 384;            // 12 warps: triple i owns rows [16i,+16); kslot = keys [64k,+64)

constexpr int SM_QH = 0;           // bf16 tiles, 128 B/row, swizzled
constexpr int SM_QL = 8192;
constexpr int SM_KH = 16384;       // 192*128 = 24576
constexpr int SM_KL = 40960;
constexpr int SM_VH = 65536;
constexpr int SM_VL = 90112;
constexpr int SMEM_BYTES = 114688; // 112 KB -> 2 CTAs/SM
// reduction scratch reuses the (dead) K region: two buffers [64][72] + sig [2][64]
constexpr int SM_RED = SM_KH;              // 2*64*72*4 = 36864 B
constexpr int SM_SIG = SM_KH + 36864;      // 512 B  (ends 53760 < SM_VH)
}

__device__ __forceinline__ uint32_t smem_u32(const void* p) {
    uint32_t a;
    asm("{ .reg .u64 t; cvta.to.shared.u64 t, %1; cvt.u32.u64 %0, t; }" : "=r"(a) : "l"(p));
    return a;
}
__device__ __forceinline__ uint32_t tile_addr(uint32_t base, int row, int c16) {
    return base + row * 128 + ((uint32_t)(c16 ^ (row & 7)) << 4);
}
__device__ __forceinline__ void split2(float x0, float x1, uint32_t& hi, uint32_t& lo) {
    __nv_bfloat16 h0 = __float2bfloat16(x0);
    __nv_bfloat16 h1 = __float2bfloat16(x1);
    __nv_bfloat16 l0 = __float2bfloat16(x0 - __bfloat162float(h0));
    __nv_bfloat16 l1 = __float2bfloat16(x1 - __bfloat162float(h1));
    hi = (uint32_t)__bfloat16_as_ushort(h0) | ((uint32_t)__bfloat16_as_ushort(h1) << 16);
    lo = (uint32_t)__bfloat16_as_ushort(l0) | ((uint32_t)__bfloat16_as_ushort(l1) << 16);
}
__device__ __forceinline__ void ldsm4(uint32_t& r0, uint32_t& r1, uint32_t& r2, uint32_t& r3,
                                      uint32_t addr) {
    asm volatile("ldmatrix.sync.aligned.m8n8.x4.shared.b16 {%0,%1,%2,%3}, [%4];"
                 : "=r"(r0), "=r"(r1), "=r"(r2), "=r"(r3) : "r"(addr));
}
__device__ __forceinline__ void ldsm4t(uint32_t& r0, uint32_t& r1, uint32_t& r2, uint32_t& r3,
                                       uint32_t addr) {
    asm volatile("ldmatrix.sync.aligned.m8n8.x4.trans.shared.b16 {%0,%1,%2,%3}, [%4];"
                 : "=r"(r0), "=r"(r1), "=r"(r2), "=r"(r3) : "r"(addr));
}
__device__ __forceinline__ void mma16816(float* d, const uint32_t* a, uint32_t b0, uint32_t b1) {
    asm volatile("mma.sync.aligned.m16n8k16.row.col.f32.bf16.bf16.f32 "
                 "{%0,%1,%2,%3}, {%4,%5,%6,%7}, {%8,%9}, {%0,%1,%2,%3};"
                 : "+f"(d[0]), "+f"(d[1]), "+f"(d[2]), "+f"(d[3])
                 : "r"(a[0]), "r"(a[1]), "r"(a[2]), "r"(a[3]), "r"(b0), "r"(b1));
}

__global__ __launch_bounds__(NT, 2)
void swa_mma_kernel(const float* __restrict__ Q,
                    const float* __restrict__ K,
                    const float* __restrict__ V,
                    float* __restrict__ O) {
    extern __shared__ char smem[];
    const uint32_t sb = smem_u32(smem);
    const int t = threadIdx.x;

    const int tile = blockIdx.x;
    const int b  = tile >> 7;              // 128 tiles per batch
    const int qt = (tile & 127) * TQ;
    const int KB = qt - 64;

    const float* qb = Q + (size_t)b * S * D;
    const float* kb = K + (size_t)b * S * D;
    const float* vb = V + (size_t)b * S * D;

    // ---------------- stage fp32 -> bf16 hi/lo tiles (swizzled) -----------
    for (int idx = t; idx < TQ * 32; idx += NT) {
        int row = idx >> 5, d2 = idx & 31;
        float2 f = *(const float2*)(qb + (size_t)(qt + row) * D + 2 * d2);
        uint32_t hi, lo;  split2(f.x, f.y, hi, lo);
        uint32_t off = row * 128 + (((uint32_t)((d2 >> 2) ^ (row & 7))) << 4) + (d2 & 3) * 4;
        *(uint32_t*)(smem + SM_QH + off) = hi;
        *(uint32_t*)(smem + SM_QL + off) = lo;
    }
    for (int idx = t; idx < KR * 32; idx += NT) {
        int row = idx >> 5, d2 = idx & 31;
        int kg = KB + row;
        float2 fk = make_float2(0.f, 0.f), fv = make_float2(0.f, 0.f);
        if (kg >= 0 && kg < S) {
            fk = *(const float2*)(kb + (size_t)kg * D + 2 * d2);
            fv = *(const float2*)(vb + (size_t)kg * D + 2 * d2);
        }
        uint32_t off = row * 128 + (((uint32_t)((d2 >> 2) ^ (row & 7))) << 4) + (d2 & 3) * 4;
        uint32_t hi, lo;
        split2(fk.x, fk.y, hi, lo);
        *(uint32_t*)(smem + SM_KH + off) = hi;
        *(uint32_t*)(smem + SM_KL + off) = lo;
        split2(fv.x, fv.y, hi, lo);
        *(uint32_t*)(smem + SM_VH + off) = hi;
        *(uint32_t*)(smem + SM_VL + off) = lo;
    }
    __syncthreads();

    const int lane  = t & 31;
    const int w     = t >> 5;              // 0..11
    const int triple = w / 3;              // 0..3: query rows [16*triple, +16)
    const int kslot  = w - 3 * triple;     // 0..2: keys [64*kslot, +64)
    const int kw     = kslot * 64;
    const int r    = lane >> 2;
    const int c    = lane & 3;
    const int rl0  = triple * 16 + r;
    const int rl1  = rl0 + 8;
    const int mat  = lane >> 3;
    const int lrow = lane & 7;

    const int lo0 = max(rl0, -KB), hi0 = min(rl0 + 128, S - 1 - KB);
    const int lo1 = max(rl1, -KB), hi1 = min(rl1 + 128, S - 1 - KB);

    // ---------------- phase 1: scores for this warp's 64 keys --------------
    float p[8][4];
    #pragma unroll
    for (int j = 0; j < 8; ++j)
        #pragma unroll
        for (int e = 0; e < 4; ++e) p[j][e] = 0.f;

    {
        uint32_t qh[4][4], ql[4][4];
        int qrow = triple * 16 + (mat & 1) * 8 + lrow;
        #pragma unroll
        for (int ks = 0; ks < 4; ++ks) {
            int c16 = ks * 2 + (mat >> 1);
            ldsm4(qh[ks][0], qh[ks][1], qh[ks][2], qh[ks][3],
                  tile_addr(sb + SM_QH, qrow, c16));
            ldsm4(ql[ks][0], ql[ks][1], ql[ks][2], ql[ks][3],
                  tile_addr(sb + SM_QL, qrow, c16));
        }
        #pragma unroll
        for (int u = 0; u < 16; ++u) {
            int g2 = u >> 2, ks = u & 3;
            int krow = kw + g2 * 16 + ((mat >> 1) & 1) * 8 + lrow;
            int c16  = ks * 2 + (mat & 1);
            uint32_t b0, b1, b2, b3;
            ldsm4(b0, b1, b2, b3, tile_addr(sb + SM_KH, krow, c16));
            mma16816(p[2 * g2],     qh[ks], b0, b1);
            mma16816(p[2 * g2 + 1], qh[ks], b2, b3);
            mma16816(p[2 * g2],     ql[ks], b0, b1);
            mma16816(p[2 * g2 + 1], ql[ks], b2, b3);
            uint32_t x0, x1, x2, x3;
            ldsm4(x0, x1, x2, x3, tile_addr(sb + SM_KL, krow, c16));
            mma16816(p[2 * g2],     qh[ks], x0, x1);
            mma16816(p[2 * g2 + 1], qh[ks], x2, x3);
        }
    }

    // ---------------- masked exp (no max-sub) ------------------------------
    float sig0 = 0.f, sig1 = 0.f;
    #pragma unroll
    for (int j = 0; j < 8; ++j) {
        int col0 = kw + 8 * j + 2 * c;
        int col1 = col0 + 1;
        float e0 = (col0 >= lo0 && col0 <= hi0) ? __expf(p[j][0] * 0.125f) : 0.f;
        float e1 = (col1 >= lo0 && col1 <= hi0) ? __expf(p[j][1] * 0.125f) : 0.f;
        float e2 = (col0 >= lo1 && col0 <= hi1) ? __expf(p[j][2] * 0.125f) : 0.f;
        float e3 = (col1 >= lo1 && col1 <= hi1) ? __expf(p[j][3] * 0.125f) : 0.f;
        sig0 += e0 + e1;
        sig1 += e2 + e3;
        p[j][0] = e0; p[j][1] = e1; p[j][2] = e2; p[j][3] = e3;
    }

    // ---------------- phase 2: PV over this warp's 64 keys -----------------
    float oacc[8][4];
    #pragma unroll
    for (int j = 0; j < 8; ++j)
        #pragma unroll
        for (int e = 0; e < 4; ++e) oacc[j][e] = 0.f;

    #pragma unroll
    for (int kk = 0; kk < 4; ++kk) {
        uint32_t ah[4], al[4];
        split2(p[2 * kk][0],     p[2 * kk][1],     ah[0], al[0]);
        split2(p[2 * kk][2],     p[2 * kk][3],     ah[1], al[1]);
        split2(p[2 * kk + 1][0], p[2 * kk + 1][1], ah[2], al[2]);
        split2(p[2 * kk + 1][2], p[2 * kk + 1][3], ah[3], al[3]);
        int vrow = kw + kk * 16 + (mat & 1) * 8 + lrow;
        #pragma unroll
        for (int g = 0; g < 4; ++g) {
            int c16 = g * 2 + (mat >> 1);
            uint32_t v0, v1, v2, v3;
            ldsm4t(v0, v1, v2, v3, tile_addr(sb + SM_VH, vrow, c16));
            mma16816(oacc[2 * g],     ah, v0, v1);
            mma16816(oacc[2 * g + 1], ah, v2, v3);
            mma16816(oacc[2 * g],     al, v0, v1);
            mma16816(oacc[2 * g + 1], al, v2, v3);
            uint32_t w0, w1, w2, w3;
            ldsm4t(w0, w1, w2, w3, tile_addr(sb + SM_VL, vrow, c16));
            mma16816(oacc[2 * g],     ah, w0, w1);
            mma16816(oacc[2 * g + 1], ah, w2, w3);
        }
    }

    // ---------------- quad-reduce sigma ------------------------------------
    sig0 += __shfl_xor_sync(0xffffffffu, sig0, 1);
    sig0 += __shfl_xor_sync(0xffffffffu, sig0, 2);
    sig1 += __shfl_xor_sync(0xffffffffu, sig1, 1);
    sig1 += __shfl_xor_sync(0xffffffffu, sig1, 2);

    // ---------------- triple reduction through smem (K region is dead) -----
    __syncthreads();
    float* red  = (float*)(smem + SM_RED);   // [2][64][72]
    float* rsig = (float*)(smem + SM_SIG);   // [2][64]
    if (kslot > 0) {
        float* rb = red + (kslot - 1) * 64 * 72;
        #pragma unroll
        for (int j = 0; j < 8; ++j) {
            *(float2*)(rb + rl0 * 72 + 8 * j + 2 * c) = make_float2(oacc[j][0], oacc[j][1]);
            *(float2*)(rb + rl1 * 72 + 8 * j + 2 * c) = make_float2(oacc[j][2], oacc[j][3]);
        }
        if (c == 0) {
            rsig[(kslot - 1) * 64 + rl0] = sig0;
            rsig[(kslot - 1) * 64 + rl1] = sig1;
        }
    }
    __syncthreads();
    if (kslot == 0) {
        float rinv0 = 1.f / (sig0 + rsig[rl0] + rsig[64 + rl0]);
        float rinv1 = 1.f / (sig1 + rsig[rl1] + rsig[64 + rl1]);
        float* o0 = O + ((size_t)b * S + qt + rl0) * D;
        float* o1 = O + ((size_t)b * S + qt + rl1) * D;
        #pragma unroll
        for (int j = 0; j < 8; ++j) {
            float2 a0 = *(float2*)(red + rl0 * 72 + 8 * j + 2 * c);
            float2 b0 = *(float2*)(red + 64 * 72 + rl0 * 72 + 8 * j + 2 * c);
            float2 a1 = *(float2*)(red + rl1 * 72 + 8 * j + 2 * c);
            float2 b1 = *(float2*)(red + 64 * 72 + rl1 * 72 + 8 * j + 2 * c);
            *(float2*)(o0 + 8 * j + 2 * c) =
                make_float2((oacc[j][0] + a0.x + b0.x) * rinv0,
                            (oacc[j][1] + a0.y + b0.y) * rinv0);
            *(float2*)(o1 + 8 * j + 2 * c) =
                make_float2((oacc[j][2] + a1.x + b1.x) * rinv1,
                            (oacc[j][3] + a1.y + b1.y) * rinv1);
        }
    }
}

extern "C" void kernel_launch(void* const* d_in, const int* in_sizes, int n_in,
                              void* d_out, int out_size) {
    const float* q = (const float*)d_in[0];
    const float* k = (const float*)d_in[1];
    const float* v = (const float*)d_in[2];
    float* o = (float*)d_out;
    (void)n_in; (void)out_size;

    cudaFuncSetAttribute(swa_mma_kernel,
                         cudaFuncAttributeMaxDynamicSharedMemorySize, SMEM_BYTES);
    const int B = in_sizes[0] / (S * D);           // 2
    swa_mma_kernel<<<B * (S / TQ), NT, SMEM_BYTES>>>(q, k, v, o);
}

// round 16
// speedup vs baseline: 1.5287x; 1.2548x over previous
#include <cuda_runtime.h>
#include <cuda_bf16.h>
#include <cstdint>

namespace {
constexpr int S  = 8192;
constexpr int D  = 64;
constexpr int TQ = 64;             // queries per CTA
constexpr int KR = 192;            // key rows staged per CTA
constexpr int NT = 384;            // 12 warps: triple T rows [16T,+16); kslot keys [16T+48k,+48)

constexpr int SM_QH = 0;           // bf16 tiles, 128 B/row, swizzled
constexpr int SM_QL = 8192;
constexpr int SM_KH = 16384;       // 192*128 = 24576
constexpr int SM_KL = 40960;
constexpr int SM_VH = 65536;
constexpr int SM_VL = 90112;
constexpr int SMEM_BYTES = 114688; // 112 KB -> 2 CTAs/SM
// reduction scratch reuses the (dead) K region
constexpr int SM_RED = SM_KH;              // 2*64*72*4 = 36864 B
constexpr int SM_SIG = SM_KH + 36864;      // 512 B
}

__device__ __forceinline__ uint32_t smem_u32(const void* p) {
    uint32_t a;
    asm("{ .reg .u64 t; cvta.to.shared.u64 t, %1; cvt.u32.u64 %0, t; }" : "=r"(a) : "l"(p));
    return a;
}
__device__ __forceinline__ uint32_t tile_addr(uint32_t base, int row, int c16) {
    return base + row * 128 + ((uint32_t)(c16 ^ (row & 7)) << 4);
}
// packed split: (x0,x1) -> hi bf16x2 + residual-lo bf16x2 (~6 inst)
__device__ __forceinline__ void split2(float x0, float x1, uint32_t& hi, uint32_t& lo) {
    asm("cvt.rn.bf16x2.f32 %0, %1, %2;" : "=r"(hi) : "f"(x1), "f"(x0));
    float h0 = __uint_as_float(hi << 16);
    float h1 = __uint_as_float(hi & 0xffff0000u);
    float l0 = x0 - h0, l1 = x1 - h1;
    asm("cvt.rn.bf16x2.f32 %0, %1, %2;" : "=r"(lo) : "f"(l1), "f"(l0));
}
__device__ __forceinline__ void ldsm4(uint32_t& r0, uint32_t& r1, uint32_t& r2, uint32_t& r3,
                                      uint32_t addr) {
    asm volatile("ldmatrix.sync.aligned.m8n8.x4.shared.b16 {%0,%1,%2,%3}, [%4];"
                 : "=r"(r0), "=r"(r1), "=r"(r2), "=r"(r3) : "r"(addr));
}
__device__ __forceinline__ void ldsm4t(uint32_t& r0, uint32_t& r1, uint32_t& r2, uint32_t& r3,
                                       uint32_t addr) {
    asm volatile("ldmatrix.sync.aligned.m8n8.x4.trans.shared.b16 {%0,%1,%2,%3}, [%4];"
                 : "=r"(r0), "=r"(r1), "=r"(r2), "=r"(r3) : "r"(addr));
}
__device__ __forceinline__ void mma16816(float* d, const uint32_t* a, uint32_t b0, uint32_t b1) {
    asm volatile("mma.sync.aligned.m16n8k16.row.col.f32.bf16.bf16.f32 "
                 "{%0,%1,%2,%3}, {%4,%5,%6,%7}, {%8,%9}, {%0,%1,%2,%3};"
                 : "+f"(d[0]), "+f"(d[1]), "+f"(d[2]), "+f"(d[3])
                 : "r"(a[0]), "r"(a[1]), "r"(a[2]), "r"(a[3]), "r"(b0), "r"(b1));
}

__global__ __launch_bounds__(NT, 2)
void swa_mma_kernel(const float* __restrict__ Q,
                    const float* __restrict__ K,
                    const float* __restrict__ V,
                    float* __restrict__ O) {
    extern __shared__ char smem[];
    const uint32_t sb = smem_u32(smem);
    const int t = threadIdx.x;

    const int tile = blockIdx.x;
    const int b  = tile >> 7;              // 128 tiles per batch
    const int qt = (tile & 127) * TQ;
    const int KB = qt - 64;

    const float* qb = Q + (size_t)b * S * D;
    const float* kb = K + (size_t)b * S * D;
    const float* vb = V + (size_t)b * S * D;

    // ------- stage fp32 -> bf16 hi/lo tiles: float4 loads, STS.64 stores ---
    for (int idx = t; idx < TQ * 16; idx += NT) {          // 16 float4 per row
        int row = idx >> 4, d4 = idx & 15;
        float4 f = *(const float4*)(qb + (size_t)(qt + row) * D + 4 * d4);
        uint32_t h0, l0, h1, l1;
        split2(f.x, f.y, h0, l0);
        split2(f.z, f.w, h1, l1);
        uint32_t off = row * 128 + (((uint32_t)((d4 >> 1) ^ (row & 7))) << 4) + (d4 & 1) * 8;
        *(uint2*)(smem + SM_QH + off) = make_uint2(h0, h1);
        *(uint2*)(smem + SM_QL + off) = make_uint2(l0, l1);
    }
    for (int idx = t; idx < KR * 16; idx += NT) {          // 8 iterations exactly
        int row = idx >> 4, d4 = idx & 15;
        int kg = KB + row;
        float4 fk = make_float4(0.f, 0.f, 0.f, 0.f);
        float4 fv = make_float4(0.f, 0.f, 0.f, 0.f);
        if (kg >= 0 && kg < S) {
            fk = *(const float4*)(kb + (size_t)kg * D + 4 * d4);
            fv = *(const float4*)(vb + (size_t)kg * D + 4 * d4);
        }
        uint32_t off = row * 128 + (((uint32_t)((d4 >> 1) ^ (row & 7))) << 4) + (d4 & 1) * 8;
        uint32_t h0, l0, h1, l1;
        split2(fk.x, fk.y, h0, l0);
        split2(fk.z, fk.w, h1, l1);
        *(uint2*)(smem + SM_KH + off) = make_uint2(h0, h1);
        *(uint2*)(smem + SM_KL + off) = make_uint2(l0, l1);
        split2(fv.x, fv.y, h0, l0);
        split2(fv.z, fv.w, h1, l1);
        *(uint2*)(smem + SM_VH + off) = make_uint2(h0, h1);
        *(uint2*)(smem + SM_VL + off) = make_uint2(l0, l1);
    }
    __syncthreads();

    const int lane  = t & 31;
    const int w     = t >> 5;              // 0..11
    const int triple = w / 3;              // 0..3: query rows [16*triple, +16)
    const int kslot  = w - 3 * triple;     // 0..2
    const int kw     = 16 * triple + 48 * kslot;   // band-tight 48-key range
    const int r    = lane >> 2;
    const int c    = lane & 3;
    const int rl0  = triple * 16 + r;
    const int rl1  = rl0 + 8;
    const int mat  = lane >> 3;
    const int lrow = lane & 7;

    const int lo0 = max(rl0, -KB), hi0 = min(rl0 + 128, S - 1 - KB);
    const int lo1 = max(rl1, -KB), hi1 = min(rl1 + 128, S - 1 - KB);

    // ---------------- phase 1: scores for this warp's 48 keys --------------
    float p[6][4];
    #pragma unroll
    for (int j = 0; j < 6; ++j)
        #pragma unroll
        for (int e = 0; e < 4; ++e) p[j][e] = 0.f;

    {
        uint32_t qh[4][4], ql[4][4];
        int qrow = triple * 16 + (mat & 1) * 8 + lrow;
        #pragma unroll
        for (int ks = 0; ks < 4; ++ks) {
            int c16 = ks * 2 + (mat >> 1);
            ldsm4(qh[ks][0], qh[ks][1], qh[ks][2], qh[ks][3],
                  tile_addr(sb + SM_QH, qrow, c16));
            ldsm4(ql[ks][0], ql[ks][1], ql[ks][2], ql[ks][3],
                  tile_addr(sb + SM_QL, qrow, c16));
        }
        #pragma unroll
        for (int u = 0; u < 12; ++u) {
            int g2 = u >> 2, ks = u & 3;                    // g2: 3 groups of 16 keys
            int krow = kw + g2 * 16 + ((mat >> 1) & 1) * 8 + lrow;
            int c16  = ks * 2 + (mat & 1);
            uint32_t b0, b1, b2, b3;
            ldsm4(b0, b1, b2, b3, tile_addr(sb + SM_KH, krow, c16));
            mma16816(p[2 * g2],     qh[ks], b0, b1);
            mma16816(p[2 * g2 + 1], qh[ks], b2, b3);
            mma16816(p[2 * g2],     ql[ks], b0, b1);
            mma16816(p[2 * g2 + 1], ql[ks], b2, b3);
            uint32_t x0, x1, x2, x3;
            ldsm4(x0, x1, x2, x3, tile_addr(sb + SM_KL, krow, c16));
            mma16816(p[2 * g2],     qh[ks], x0, x1);
            mma16816(p[2 * g2 + 1], qh[ks], x2, x3);
        }
    }

    // ---------------- masked exp (no max-sub) ------------------------------
    float sig0 = 0.f, sig1 = 0.f;
    #pragma unroll
    for (int j = 0; j < 6; ++j) {
        int col0 = kw + 8 * j + 2 * c;
        int col1 = col0 + 1;
        float e0 = (col0 >= lo0 && col0 <= hi0) ? __expf(p[j][0] * 0.125f) : 0.f;
        float e1 = (col1 >= lo0 && col1 <= hi0) ? __expf(p[j][1] * 0.125f) : 0.f;
        float e2 = (col0 >= lo1 && col0 <= hi1) ? __expf(p[j][2] * 0.125f) : 0.f;
        float e3 = (col1 >= lo1 && col1 <= hi1) ? __expf(p[j][3] * 0.125f) : 0.f;
        sig0 += e0 + e1;
        sig1 += e2 + e3;
        p[j][0] = e0; p[j][1] = e1; p[j][2] = e2; p[j][3] = e3;
    }

    // ---------------- phase 2: PV over this warp's 48 keys -----------------
    float oacc[8][4];
    #pragma unroll
    for (int j = 0; j < 8; ++j)
        #pragma unroll
        for (int e = 0; e < 4; ++e) oacc[j][e] = 0.f;

    #pragma unroll
    for (int kk = 0; kk < 3; ++kk) {
        uint32_t ah[4], al[4];
        split2(p[2 * kk][0],     p[2 * kk][1],     ah[0], al[0]);
        split2(p[2 * kk][2],     p[2 * kk][3],     ah[1], al[1]);
        split2(p[2 * kk + 1][0], p[2 * kk + 1][1], ah[2], al[2]);
        split2(p[2 * kk + 1][2], p[2 * kk + 1][3], ah[3], al[3]);
        int vrow = kw + kk * 16 + (mat & 1) * 8 + lrow;
        #pragma unroll
        for (int g = 0; g < 4; ++g) {
            int c16 = g * 2 + (mat >> 1);
            uint32_t v0, v1, v2, v3;
            ldsm4t(v0, v1, v2, v3, tile_addr(sb + SM_VH, vrow, c16));
            mma16816(oacc[2 * g],     ah, v0, v1);
            mma16816(oacc[2 * g + 1], ah, v2, v3);
            mma16816(oacc[2 * g],     al, v0, v1);
            mma16816(oacc[2 * g + 1], al, v2, v3);
            uint32_t w0, w1, w2, w3;
            ldsm4t(w0, w1, w2, w3, tile_addr(sb + SM_VL, vrow, c16));
            mma16816(oacc[2 * g],     ah, w0, w1);
            mma16816(oacc[2 * g + 1], ah, w2, w3);
        }
    }

    // ---------------- quad-reduce sigma ------------------------------------
    sig0 += __shfl_xor_sync(0xffffffffu, sig0, 1);
    sig0 += __shfl_xor_sync(0xffffffffu, sig0, 2);
    sig1 += __shfl_xor_sync(0xffffffffu, sig1, 1);
    sig1 += __shfl_xor_sync(0xffffffffu, sig1, 2);

    // ---------------- triple reduction through smem (K region is dead) -----
    __syncthreads();
    float* red  = (float*)(smem + SM_RED);   // [2][64][72]
    float* rsig = (float*)(smem + SM_SIG);   // [2][64]
    if (kslot > 0) {
        float* rb = red + (kslot - 1) * 64 * 72;
        #pragma unroll
        for (int j = 0; j < 8; ++j) {
            *(float2*)(rb + rl0 * 72 + 8 * j + 2 * c) = make_float2(oacc[j][0], oacc[j][1]);
            *(float2*)(rb + rl1 * 72 + 8 * j + 2 * c) = make_float2(oacc[j][2], oacc[j][3]);
        }
        if (c == 0) {
            rsig[(kslot - 1) * 64 + rl0] = sig0;
            rsig[(kslot - 1) * 64 + rl1] = sig1;
        }
    }
    __syncthreads();
    if (kslot == 0) {
        float rinv0 = 1.f / (sig0 + rsig[rl0] + rsig[64 + rl0]);
        float rinv1 = 1.f / (sig1 + rsig[rl1] + rsig[64 + rl1]);
        float* o0 = O + ((size_t)b * S + qt + rl0) * D;
        float* o1 = O + ((size_t)b * S + qt + rl1) * D;
        #pragma unroll
        for (int j = 0; j < 8; ++j) {
            float2 a0 = *(float2*)(red + rl0 * 72 + 8 * j + 2 * c);
            float2 b0 = *(float2*)(red + 64 * 72 + rl0 * 72 + 8 * j + 2 * c);
            float2 a1 = *(float2*)(red + rl1 * 72 + 8 * j + 2 * c);
            float2 b1 = *(float2*)(red + 64 * 72 + rl1 * 72 + 8 * j + 2 * c);
            *(float2*)(o0 + 8 * j + 2 * c) =
                make_float2((oacc[j][0] + a0.x + b0.x) * rinv0,
                            (oacc[j][1] + a0.y + b0.y) * rinv0);
            *(float2*)(o1 + 8 * j + 2 * c) =
                make_float2((oacc[j][2] + a1.x + b1.x) * rinv1,
                            (oacc[j][3] + a1.y + b1.y) * rinv1);
        }
    }
}

extern "C" void kernel_launch(void* const* d_in, const int* in_sizes, int n_in,
                              void* d_out, int out_size) {
    const float* q = (const float*)d_in[0];
    const float* k = (const float*)d_in[1];
    const float* v = (const float*)d_in[2];
    float* o = (float*)d_out;
    (void)n_in; (void)out_size;

    cudaFuncSetAttribute(swa_mma_kernel,
                         cudaFuncAttributeMaxDynamicSharedMemorySize, SMEM_BYTES);
    const int B = in_sizes[0] / (S * D);           // 2
    swa_mma_kernel<<<B * (S / TQ), NT, SMEM_BYTES>>>(q, k, v, o);
}